// round 15
// baseline (speedup 1.0000x reference)
#include <cuda_runtime.h>
#include <cuda_fp16.h>
#include <cstdint>

// Based linear attention == causal attention with phi(s)=s+0.5*s^2, s=scale*(q.k).
// Warp-level mma.sync (fp16 m16n8k16, fp32 accum), single-rounded fp16 operands
// (calibrated rel_err ~4.3e-4 < 1e-3).
// R15: R14 (warp-autonomous 32-thread CTAs, 32 q-rows, 2-stage ring, no
// __syncthreads) with the Q-conversion loop FIXED: 512 float4 chunks (16 iters),
// not 256 — R14 left Q rows 16..31 uninitialized -> NaN.

#define BB 2
#define HH 16
#define SEQ 2048
#define DD 64
#define QROWS 32
#define KROWS 32
#define NQT (SEQ / QROWS)   // 64
#define NBH (BB * HH)       // 32
#define TOTAL_ELEMS (NBH * SEQ * DD)
#define TOTAL_F4    (TOTAL_ELEMS / 4)

// fp16 K/V scratch (uint2 = 4 halfs), element order == original fp32 order
__device__ uint2 g_kh[TOTAL_F4];
__device__ uint2 g_vh[TOTAL_F4];

// smem: Q 4KB | 2-stage ring of (K 4KB + V 4KB)
#define SOFF_Q 0
#define RING_OFF 4096
#define STAGE_BYTES 8192
#define SMEM_TOTAL (4096 + 2 * STAGE_BYTES)   // 20480

__device__ __forceinline__ uint32_t smem_u32(const void* p) {
    uint32_t a;
    asm("{ .reg .u64 t; cvta.to.shared.u64 t, %1; cvt.u32.u64 %0, t; }" : "=r"(a) : "l"(p));
    return a;
}

// byte swizzle for 128B rows: XOR row[2:0] into 16B-chunk index (8B-stable)
__device__ __forceinline__ uint32_t swz(uint32_t b) { return b ^ ((b >> 3) & 0x70); }

__device__ __forceinline__ void mma_f16(float* c, const uint32_t* a,
                                        uint32_t b0, uint32_t b1) {
    asm volatile(
        "mma.sync.aligned.m16n8k16.row.col.f32.f16.f16.f32 "
        "{%0,%1,%2,%3}, {%4,%5,%6,%7}, {%8,%9}, {%0,%1,%2,%3};"
        : "+f"(c[0]), "+f"(c[1]), "+f"(c[2]), "+f"(c[3])
        : "r"(a[0]), "r"(a[1]), "r"(a[2]), "r"(a[3]), "r"(b0), "r"(b1));
}

__device__ __forceinline__ void ldsm4(uint32_t* r, uint32_t addr) {
    asm volatile("ldmatrix.sync.aligned.m8n8.x4.shared.b16 {%0,%1,%2,%3}, [%4];"
                 : "=r"(r[0]), "=r"(r[1]), "=r"(r[2]), "=r"(r[3]) : "r"(addr));
}
__device__ __forceinline__ void ldsm4t(uint32_t* r, uint32_t addr) {
    asm volatile("ldmatrix.sync.aligned.m8n8.x4.trans.shared.b16 {%0,%1,%2,%3}, [%4];"
                 : "=r"(r[0]), "=r"(r[1]), "=r"(r[2]), "=r"(r[3]) : "r"(addr));
}

__device__ __forceinline__ void cp_async16(uint32_t smem_dst, const void* gptr) {
    asm volatile("cp.async.cg.shared.global [%0], [%1], 16;"
                 :: "r"(smem_dst), "l"(gptr) : "memory");
}
#define CP_COMMIT() asm volatile("cp.async.commit_group;" ::: "memory")
#define CP_WAIT1()  asm volatile("cp.async.wait_group 1;" ::: "memory")
#define CP_WAIT0()  asm volatile("cp.async.wait_group 0;" ::: "memory")

// pack (x,y) into one half2 word
__device__ __forceinline__ uint32_t pack2h(float x, float y) {
    __half2 h = __floats2half2_rn(x, y);
    return *reinterpret_cast<uint32_t*>(&h);
}

// ---- prepass: round K, V to fp16 scratch ----
__global__ __launch_bounds__(256)
void conv_kv_kernel(const float* __restrict__ k, const float* __restrict__ v) {
    int idx = blockIdx.x * 256 + threadIdx.x;     // float4 index
    float4 kv = reinterpret_cast<const float4*>(k)[idx];
    g_kh[idx] = make_uint2(pack2h(kv.x, kv.y), pack2h(kv.z, kv.w));
    float4 vv = reinterpret_cast<const float4*>(v)[idx];
    g_vh[idx] = make_uint2(pack2h(vv.x, vv.y), pack2h(vv.z, vv.w));
}

__global__ __launch_bounds__(32, 16)
void based_mma_kernel(const float* __restrict__ q, float* __restrict__ out)
{
    extern __shared__ char sm[];
    const uint32_t sbase = smem_u32(sm);

    const int lane = threadIdx.x;
    const int g    = lane >> 2;
    const int t4   = lane & 3;

    const int bh = blockIdx.y;
    const int qt = (NQT - 1) - blockIdx.x;   // big q-tiles first
    const size_t head = (size_t)bh * SEQ * DD;
    const size_t headB = head * 2;           // byte offset into g_* scratch
    const int nkt = qt + 1;                  // 32-key tiles, causal

    const char* khB = (const char*)g_kh + headB;
    const char* vhB = (const char*)g_vh + headB;

    // 8 x 16B chunks per lane per 4KB sub-tile
    auto issue_tile = [&](int kt) {
        uint32_t sb = sbase + RING_OFF + (kt & 1) * STAGE_BYTES;
        size_t tb = (size_t)kt * 4096;    // 32*64*2 bytes per tile
        #pragma unroll
        for (int i = 0; i < 8; ++i) {
            int c = lane + i * 32;                 // chunk 0..255
            uint32_t so = swz((uint32_t)(c * 16));
            cp_async16(sb + so,        khB + tb + c * 16);
            cp_async16(sb + 4096 + so, vhB + tb + c * 16);
        }
        CP_COMMIT();
    };

    // ---- prologue: stage tiles 0 (and 1); convert Q fp32 -> fp16 smem ----
    issue_tile(0);
    if (nkt > 1) issue_tile(1);
    {
        const float scale = 0.125f;
        const float4* qg = reinterpret_cast<const float4*>(q + head + (size_t)qt * QROWS * DD);
        #pragma unroll
        for (int i = 0; i < 16; ++i) {        // FIXED: 512 float4 chunks, not 256
            int idx = lane + i * 32;          // float4 index 0..511
            int row = idx >> 4, c4 = idx & 15;
            float4 v = qg[idx];
            uint2 hv = make_uint2(pack2h(v.x * scale, v.y * scale),
                                  pack2h(v.z * scale, v.w * scale));
            *reinterpret_cast<uint2*>(sm + SOFF_Q + swz((uint32_t)(row * 128 + c4 * 8))) = hv;
        }
    }
    __syncwarp();

    float oacc[2][8][4] = {};   // [row-block][8-col block of D][frag]

    const uint32_t sw = (lane & 7) << 4;
    const int rowK = ((lane >> 3) & 1) * 8 + (lane & 7);
    const int colK = (lane >> 4) * 16;
    const int rowV = ((lane >> 4) & 1) * 8 + (lane & 7);
    const int colV = ((lane >> 3) & 1) * 16;
    const uint32_t qb = sbase + SOFF_Q;

    for (int kt = 0; kt < nkt; ++kt) {
        // Program order within the single warp makes stage reuse race-free:
        // tile kt-1's ldsm reads all completed before we issue tile kt+1.
        if (kt + 1 < nkt) {
            if (kt >= 1) issue_tile(kt + 1);
            CP_WAIT1();          // tile kt landed; kt+1 still in flight
        } else {
            CP_WAIT0();
        }
        __syncwarp();

        const uint32_t kb = sbase + RING_OFF + (kt & 1) * STAGE_BYTES;
        const uint32_t vb = kb + 4096;

        // ---- GEMM1: S[32x32] = Q_h * K_h^T (Q A-frags from smem per kk) ----
        float sacc[2][4][4] = {};
        #pragma unroll
        for (int kk = 0; kk < 4; ++kk) {
            uint32_t colo = ((uint32_t)(32 * kk + colK)) ^ sw;
            uint32_t a0r[4], a1r[4], br0[4], br1[4];
            ldsm4(a0r, qb + (uint32_t)(rowK * 128) + colo);
            ldsm4(a1r, qb + (uint32_t)((16 + rowK) * 128) + colo);
            ldsm4(br0, kb + (uint32_t)(rowK * 128) + colo);
            ldsm4(br1, kb + (uint32_t)((16 + rowK) * 128) + colo);
            mma_f16(sacc[0][0], a0r, br0[0], br0[2]);
            mma_f16(sacc[0][1], a0r, br0[1], br0[3]);
            mma_f16(sacc[0][2], a0r, br1[0], br1[2]);
            mma_f16(sacc[0][3], a0r, br1[1], br1[3]);
            mma_f16(sacc[1][0], a1r, br0[0], br0[2]);
            mma_f16(sacc[1][1], a1r, br0[1], br0[3]);
            mma_f16(sacc[1][2], a1r, br1[0], br1[2]);
            mma_f16(sacc[1][3], a1r, br1[1], br1[3]);
        }

        // ---- phi + GEMM2 per 16-key step: O += phi_h * V_h ----
        const bool edge = (kt == qt);    // only the diagonal tile needs masking
        #pragma unroll
        for (int kk2 = 0; kk2 < 2; ++kk2) {
            uint32_t ah0[4], ah1[4];
            #pragma unroll
            for (int rb = 0; rb < 2; ++rb) {
                uint32_t* ah = rb ? ah1 : ah0;
                #pragma unroll
                for (int half = 0; half < 2; ++half) {    // nb = 2*kk2+half
                    int nb = 2 * kk2 + half;
                    float e[4];
                    #pragma unroll
                    for (int u = 0; u < 4; ++u) {
                        float s = sacc[rb][nb][u];
                        float p = fmaf(0.5f * s, s, s);
                        if (edge) {
                            int colg = 8 * nb + 2 * t4 + (u & 1);        // key within tile
                            int rowg = 16 * rb + g + ((u & 2) ? 8 : 0);  // row within tile
                            if (colg > rowg) p = 0.0f;                   // kt==qt: same base
                        }
                        e[u] = p;
                    }
                    ah[2 * half]     = pack2h(e[0], e[1]);
                    ah[2 * half + 1] = pack2h(e[2], e[3]);
                }
            }
            #pragma unroll
            for (int p = 0; p < 4; ++p) {
                uint32_t off = (uint32_t)((16 * kk2 + rowV) * 128) + (((uint32_t)(32 * p + colV)) ^ sw);
                uint32_t vr[4];
                ldsm4t(vr, vb + off);
                mma_f16(oacc[0][2 * p],     ah0, vr[0], vr[2]);
                mma_f16(oacc[0][2 * p + 1], ah0, vr[1], vr[3]);
                mma_f16(oacc[1][2 * p],     ah1, vr[0], vr[2]);
                mma_f16(oacc[1][2 * p + 1], ah1, vr[1], vr[3]);
            }
        }
    }

    // ---- store O fragments (32 rows x 64 cols) ----
    float* og = out + head + (size_t)qt * QROWS * DD;
    #pragma unroll
    for (int rb = 0; rb < 2; ++rb) {
        int row0 = 16 * rb + g;
        #pragma unroll
        for (int nb = 0; nb < 8; ++nb) {
            int col = nb * 8 + 2 * t4;
            *reinterpret_cast<float2*>(og + (size_t)row0 * DD + col) =
                make_float2(oacc[rb][nb][0], oacc[rb][nb][1]);
            *reinterpret_cast<float2*>(og + (size_t)(row0 + 8) * DD + col) =
                make_float2(oacc[rb][nb][2], oacc[rb][nb][3]);
        }
    }
}

extern "C" void kernel_launch(void* const* d_in, const int* in_sizes, int n_in,
                              void* d_out, int out_size) {
    const float* q = (const float*)d_in[0];
    const float* k = (const float*)d_in[1];
    const float* v = (const float*)d_in[2];
    float* out = (float*)d_out;

    static bool attr_set = false;
    if (!attr_set) {
        cudaFuncSetAttribute(based_mma_kernel,
                             cudaFuncAttributeMaxDynamicSharedMemorySize, SMEM_TOTAL);
        attr_set = true;
    }

    conv_kv_kernel<<<TOTAL_F4 / 256, 256>>>(k, v);
    dim3 grid(NQT, NBH);
    based_mma_kernel<<<grid, 32, SMEM_TOTAL>>>(q, out);
}